// round 12
// baseline (speedup 1.0000x reference)
#include <cuda_runtime.h>
#include <cuda_fp16.h>

#define NN 200000
#define NE 6400000
#define FIN 128
#define HID 16

// ---- scratch (device globals; no allocation allowed) ----
// INVARIANT across graph replays: g_agg == 0 on entry.
// (static zero-init on call 1; mid_kernel re-zeros after pass-1 read,
//  final_kernel re-zeros after pass-2 read.)
__device__ __align__(16) __half g_h[NN * HID];   // layer features, fp16 payload (32B rows)
__device__ __align__(16) float  g_agg[NN * HID]; // scatter-add accumulator, fp32 (64B rows)

// ---------------------------------------------------------------------------
// K0: h1pre = x @ W1  (N x 128 @ 128 x 16), warp per node. fp16 output.
// ---------------------------------------------------------------------------
__global__ void gemm1_kernel(const float* __restrict__ x,
                             const float* __restrict__ W1,
                             __half* __restrict__ out) {
    __shared__ __align__(16) float sWt[HID * FIN];
    for (int i = threadIdx.x; i < HID * FIN; i += blockDim.x) {
        int j = i / FIN, k = i % FIN;
        sWt[i] = W1[k * HID + j];
    }
    __syncthreads();

    int gwarp = (blockIdx.x * blockDim.x + threadIdx.x) >> 5;
    int lane  = threadIdx.x & 31;
    if (gwarp >= NN) return;

    float4 xv = __ldcs(((const float4*)(x + (size_t)gwarp * FIN)) + lane);

    float acc[HID];
    const float4* sWt4 = (const float4*)sWt;
#pragma unroll
    for (int j = 0; j < HID; j++) {
        float4 wv = sWt4[j * (FIN / 4) + lane];
        acc[j] = xv.x * wv.x + xv.y * wv.y + xv.z * wv.z + xv.w * wv.w;
    }
#pragma unroll
    for (int j = 0; j < HID; j++) {
#pragma unroll
        for (int off = 16; off; off >>= 1)
            acc[j] += __shfl_xor_sync(0xFFFFFFFFu, acc[j], off);
    }
    if (lane < HID) out[(size_t)gwarp * HID + lane] = __float2half_rn(acc[lane]);
}

// ---------------------------------------------------------------------------
// Edge scatter: agg[dst] += w * h[src], fp16 gather payload, fp32 RED.
// 4 lanes per edge; lane j loads 8B (4 halves) of the 32B fp16 row -> one
// coalesced 32B line-visit per edge (half the former gather traffic), then
// one red.v4.f32 per lane (64B fp32 accumulate, unchanged precision).
// ---------------------------------------------------------------------------
__global__ void scatter4_kernel(const int* __restrict__ src,
                                const int* __restrict__ dst,
                                const float* __restrict__ w,
                                const __half* __restrict__ h,
                                float* __restrict__ agg) {
    long long t = (long long)blockIdx.x * blockDim.x + threadIdx.x;
    int e = (int)(t >> 2);
    int j = (int)(t & 3);
    if (e >= NE) return;

    int   s  = __ldcs(src + e);   // 4-lane broadcast within warp
    int   d  = __ldcs(dst + e);
    float we = __ldcs(w + e);

    uint2 raw = __ldg(((const uint2*)(h + (size_t)s * HID)) + j);   // 4 halves
    __half2 ha = *reinterpret_cast<const __half2*>(&raw.x);
    __half2 hb = *reinterpret_cast<const __half2*>(&raw.y);
    float2 fa = __half22float2(ha);
    float2 fb = __half22float2(hb);

    float* ad = agg + (size_t)d * HID + 4 * j;
    asm volatile(
        "red.global.add.v4.f32 [%0], {%1, %2, %3, %4};"
        :: "l"(ad), "f"(fa.x * we), "f"(fa.y * we), "f"(fb.x * we), "f"(fb.y * we)
        : "memory");
}

// ---------------------------------------------------------------------------
// K2: h2pre = relu(agg + b1) @ W2 (fp16 out) ; RESETS agg to zero for pass 2.
// ---------------------------------------------------------------------------
__global__ void mid_kernel(float* __restrict__ agg,
                           const float* __restrict__ b1,
                           const float* __restrict__ W2,
                           __half* __restrict__ out) {
    __shared__ __align__(16) float sW[HID * HID];
    __shared__ float sb[HID];
    for (int i = threadIdx.x; i < HID * HID; i += blockDim.x) sW[i] = W2[i];
    if (threadIdx.x < HID) sb[threadIdx.x] = b1[threadIdx.x];
    __syncthreads();

    int n = blockIdx.x * blockDim.x + threadIdx.x;
    if (n >= NN) return;

    float a[HID];
    float4* ap = (float4*)(agg + (size_t)n * HID);
#pragma unroll
    for (int i = 0; i < 4; i++) {
        float4 v = ap[i];
        a[4 * i + 0] = v.x; a[4 * i + 1] = v.y;
        a[4 * i + 2] = v.z; a[4 * i + 3] = v.w;
    }
    // reset for the next scatter pass (fused zero)
#pragma unroll
    for (int i = 0; i < 4; i++) ap[i] = make_float4(0.f, 0.f, 0.f, 0.f);

#pragma unroll
    for (int k = 0; k < HID; k++) a[k] = fmaxf(a[k] + sb[k], 0.f);

    __half2 o2[HID / 2];
#pragma unroll
    for (int j = 0; j < HID; j += 2) {
        float acc0 = 0.f, acc1 = 0.f;
#pragma unroll
        for (int k = 0; k < HID; k++) {
            acc0 += a[k] * sW[k * HID + j];
            acc1 += a[k] * sW[k * HID + j + 1];
        }
        o2[j / 2] = __floats2half2_rn(acc0, acc1);
    }
    // HID halves = 32B per row -> two 16B stores
    uint4* op = (uint4*)(out + (size_t)n * HID);
    op[0] = *reinterpret_cast<uint4*>(&o2[0]);
    op[1] = *reinterpret_cast<uint4*>(&o2[4]);
}

// ---------------------------------------------------------------------------
// K4: out = relu(agg + b2) @ Wd + bd ; RESETS agg to zero for next replay.
// ---------------------------------------------------------------------------
__global__ void final_kernel(float* __restrict__ agg,
                             const float* __restrict__ b2,
                             const float* __restrict__ Wd,
                             const float* __restrict__ bd,
                             float* __restrict__ out) {
    __shared__ float sb[HID], sw[HID], sbd;
    if (threadIdx.x < HID) { sb[threadIdx.x] = b2[threadIdx.x]; sw[threadIdx.x] = Wd[threadIdx.x]; }
    if (threadIdx.x == 0) sbd = bd[0];
    __syncthreads();

    int n = blockIdx.x * blockDim.x + threadIdx.x;
    if (n >= NN) return;

    float4* ap = (float4*)(agg + (size_t)n * HID);
    float acc = sbd;
#pragma unroll
    for (int i = 0; i < 4; i++) {
        float4 v = ap[i];
        acc += fmaxf(v.x + sb[4 * i + 0], 0.f) * sw[4 * i + 0];
        acc += fmaxf(v.y + sb[4 * i + 1], 0.f) * sw[4 * i + 1];
        acc += fmaxf(v.z + sb[4 * i + 2], 0.f) * sw[4 * i + 2];
        acc += fmaxf(v.w + sb[4 * i + 3], 0.f) * sw[4 * i + 3];
    }
    // restore invariant for the next replay
#pragma unroll
    for (int i = 0; i < 4; i++) ap[i] = make_float4(0.f, 0.f, 0.f, 0.f);

    out[n] = acc;
}

// ---------------------------------------------------------------------------
extern "C" void kernel_launch(void* const* d_in, const int* in_sizes, int n_in,
                              void* d_out, int out_size) {
    const float* x   = (const float*)d_in[0];
    const int*   src = (const int*)d_in[1];
    const int*   dst = (const int*)d_in[2];
    const float* ew  = (const float*)d_in[3];
    const float* W1  = (const float*)d_in[4];
    const float* b1  = (const float*)d_in[5];
    const float* W2  = (const float*)d_in[6];
    const float* b2  = (const float*)d_in[7];
    const float* Wd  = (const float*)d_in[8];
    const float* bd  = (const float*)d_in[9];
    float* out = (float*)d_out;

    __half *hP;
    float *aggP;
    cudaGetSymbolAddress((void**)&hP,   g_h);
    cudaGetSymbolAddress((void**)&aggP, g_agg);

    const int TPB = 256;
    const int gemm1_blocks = (NN * 32 + TPB - 1) / TPB;        // warp per node
    const long long scat_threads = (long long)NE * 4;          // 4 lanes per edge
    const int scat_blocks  = (int)((scat_threads + TPB - 1) / TPB);
    const int node_blocks  = (NN + TPB - 1) / TPB;

    // K0: feature transform -> fp16 h (agg already zero by invariant)
    gemm1_kernel<<<gemm1_blocks, TPB>>>(x, W1, hP);
    // K1: layer-1 scatter (fp16 gather, fp32 RED)
    scatter4_kernel<<<scat_blocks, TPB>>>(src, dst, ew, hP, aggP);
    // K2: relu(agg+b1)@W2 -> fp16 h ; re-zeros agg
    mid_kernel<<<node_blocks, TPB>>>(aggP, b1, W2, hP);
    // K3 (profiled): layer-2 scatter
    scatter4_kernel<<<scat_blocks, TPB>>>(src, dst, ew, hP, aggP);
    // K4: relu(agg+b2)@Wd+bd -> out ; re-zeros agg for next replay
    final_kernel<<<node_blocks, TPB>>>(aggP, b2, Wd, bd, out);
}